// round 1
// baseline (speedup 1.0000x reference)
#include <cuda_runtime.h>
#include <math.h>

// ---------------- problem constants ----------------
#define BB     64
#define HH     56
#define WWID   56
#define CC     256
#define WS     7
#define SHIFT  3
#define HEADS  8
#define HD     32
#define NWIN   49               // tokens per window
#define NW     64               // windows per image (8x8)
#define BWIN   (BB*NW)          // 4096
#define MROWS  (BWIN*NWIN)      // 200704 == B*H*W
#define HID    1024
#define QSCALE 0.17677669529663689f   // 32^-0.5

// ---------------- scratch (device globals; no allocation allowed) ----------------
__device__ float g_ywin[(size_t)MROWS*CC];   // LN1+shift+window-partitioned activations
__device__ float g_q[(size_t)MROWS*CC];      // (B_,HEADS,N,HD), pre-scaled
__device__ float g_k[(size_t)MROWS*CC];
__device__ float g_v[(size_t)MROWS*CC];
__device__ float g_ao[(size_t)MROWS*CC];     // attention out, (B_*N, C) head-interleaved
__device__ float g_ln2[(size_t)MROWS*CC];
__device__ float g_h1[(size_t)MROWS*HID];    // fc1+gelu output

// ---------------- LN helpers ----------------
__device__ __forceinline__ void block_reduce_2(float &s, float &q) {
    #pragma unroll
    for (int o = 16; o > 0; o >>= 1) {
        s += __shfl_xor_sync(0xffffffffu, s, o);
        q += __shfl_xor_sync(0xffffffffu, q, o);
    }
    __shared__ float ss[8], sq[8];
    int lane = threadIdx.x & 31, wid = threadIdx.x >> 5;
    if (lane == 0) { ss[wid] = s; sq[wid] = q; }
    __syncthreads();
    float ts = 0.f, tq = 0.f;
    #pragma unroll
    for (int k = 0; k < 8; k++) { ts += ss[k]; tq += sq[k]; }
    s = ts; q = tq;
}

// LN1 + cyclic shift (-3,-3) + window partition, writes g_ywin row-major (M, C)
__global__ void ln1_gather(const float* __restrict__ x,
                           const float* __restrict__ gam,
                           const float* __restrict__ bet) {
    int r = blockIdx.x, t = threadIdx.x;
    int b_ = r / NWIN, n = r % NWIN;
    int b = b_ >> 6, widx = b_ & 63;
    int wh = widx >> 3, ww = widx & 7;
    int i = n / WS, j = n % WS;
    int h = (wh*WS + i + SHIFT) % HH;
    int w = (ww*WS + j + SHIFT) % WWID;
    size_t src = ((size_t)b*(HH*WWID) + (size_t)h*WWID + w)*CC + t;
    float v = x[src];
    float s = v, q = v*v;
    block_reduce_2(s, q);
    float mean = s * (1.f/CC);
    float var  = q * (1.f/CC) - mean*mean;
    float rstd = rsqrtf(var + 1e-5f);
    g_ywin[(size_t)r*CC + t] = (v - mean)*rstd*gam[t] + bet[t];
}

// LN2 over x_mid (stored in d_out), writes g_ln2
__global__ void ln2_kernel(const float* __restrict__ xin,
                           const float* __restrict__ gam,
                           const float* __restrict__ bet) {
    int r = blockIdx.x, t = threadIdx.x;
    float v = xin[(size_t)r*CC + t];
    float s = v, q = v*v;
    block_reduce_2(s, q);
    float mean = s * (1.f/CC);
    float var  = q * (1.f/CC) - mean*mean;
    float rstd = rsqrtf(var + 1e-5f);
    g_ln2[(size_t)r*CC + t] = (v - mean)*rstd*gam[t] + bet[t];
}

// ---------------- SGEMM: C[m,n] = sum_k A[m,k]*Bw[n,k]  (NT, both K-contiguous) ----------------
// BM=BN=128, BK=16, 256 threads, 8x8 per thread. M%128==0, N%128==0, K%16==0 (all hold here).
// ASEL selects A from device globals; EPI selects fused epilogue.
template<int EPI, int ASEL>
__global__ void __launch_bounds__(256) sgemm_nt(const float* __restrict__ Bw,
                                                const float* __restrict__ bias,
                                                const float* __restrict__ add_src,
                                                float* __restrict__ Cout,
                                                int K) {
    const float* A;
    if      (ASEL == 0) A = g_ywin;
    else if (ASEL == 1) A = g_ao;
    else if (ASEL == 2) A = g_ln2;
    else                A = g_h1;

    __shared__ float As[16][132];
    __shared__ float Bs[16][132];

    int bm = blockIdx.y, bn = blockIdx.x;
    int t  = threadIdx.x;
    int tx = t & 15, ty = t >> 4;
    int lr = t >> 2;            // 0..63
    int lc = (t & 3) << 2;      // 0,4,8,12

    const float* Ablk = A  + (size_t)(bm*128)*K;
    const float* Bblk = Bw + (size_t)(bn*128)*K;

    float acc[8][8];
    #pragma unroll
    for (int i = 0; i < 8; i++)
        #pragma unroll
        for (int j = 0; j < 8; j++) acc[i][j] = 0.f;

    for (int k0 = 0; k0 < K; k0 += 16) {
        float4 a0 = *(const float4*)(Ablk + (size_t)lr      *K + k0 + lc);
        float4 a1 = *(const float4*)(Ablk + (size_t)(lr+64)*K + k0 + lc);
        float4 b0 = *(const float4*)(Bblk + (size_t)lr      *K + k0 + lc);
        float4 b1 = *(const float4*)(Bblk + (size_t)(lr+64)*K + k0 + lc);
        __syncthreads();
        As[lc+0][lr]    = a0.x; As[lc+1][lr]    = a0.y; As[lc+2][lr]    = a0.z; As[lc+3][lr]    = a0.w;
        As[lc+0][lr+64] = a1.x; As[lc+1][lr+64] = a1.y; As[lc+2][lr+64] = a1.z; As[lc+3][lr+64] = a1.w;
        Bs[lc+0][lr]    = b0.x; Bs[lc+1][lr]    = b0.y; Bs[lc+2][lr]    = b0.z; Bs[lc+3][lr]    = b0.w;
        Bs[lc+0][lr+64] = b1.x; Bs[lc+1][lr+64] = b1.y; Bs[lc+2][lr+64] = b1.z; Bs[lc+3][lr+64] = b1.w;
        __syncthreads();
        #pragma unroll
        for (int kk = 0; kk < 16; kk++) {
            float ar[8], br[8];
            *(float4*)&ar[0] = *(const float4*)&As[kk][ty*8];
            *(float4*)&ar[4] = *(const float4*)&As[kk][ty*8+4];
            *(float4*)&br[0] = *(const float4*)&Bs[kk][tx*8];
            *(float4*)&br[4] = *(const float4*)&Bs[kk][tx*8+4];
            #pragma unroll
            for (int i = 0; i < 8; i++)
                #pragma unroll
                for (int j = 0; j < 8; j++)
                    acc[i][j] = fmaf(ar[i], br[j], acc[i][j]);
        }
    }

    int rm = bm*128 + ty*8;
    int cn = bn*128 + tx*8;

    #pragma unroll
    for (int i = 0; i < 8; i++) {
        int m = rm + i;
        // per-row scatter data (only used by some epilogues)
        int b_ = m / NWIN, n = m % NWIN;
        if (EPI == 0) {
            // qkv: split into q/k/v with layout (B_,HEADS,N,HD); scale q
            #pragma unroll
            for (int j = 0; j < 8; j++) {
                int jj = cn + j;
                float val = acc[i][j] + bias[jj];
                int part = jj >> 8;       // constant within a block
                int c = jj & 255;
                int head = c >> 5, d = c & 31;
                size_t dst = ((size_t)(b_*HEADS + head)*NWIN + n)*HD + d;
                if      (part == 0) g_q[dst] = val * QSCALE;
                else if (part == 1) g_k[dst] = val;
                else                g_v[dst] = val;
            }
        } else if (EPI == 1) {
            // proj: window-reverse + reverse shift scatter, + residual x, -> Cout (d_out)
            int b = b_ >> 6, widx = b_ & 63;
            int wh = widx >> 3, ww = widx & 7;
            int ii = n / WS, jj2 = n % WS;
            int h = (wh*WS + ii + SHIFT) % HH;
            int w = (ww*WS + jj2 + SHIFT) % WWID;
            size_t drow = (size_t)b*(HH*WWID) + (size_t)h*WWID + w;
            #pragma unroll
            for (int j = 0; j < 8; j++) {
                int jj = cn + j;
                float val = acc[i][j] + bias[jj];
                Cout[drow*CC + jj] = add_src[drow*CC + jj] + val;
            }
        } else if (EPI == 2) {
            // fc1 + fast gelu -> g_h1
            #pragma unroll
            for (int j = 0; j < 8; j++) {
                int jj = cn + j;
                float val = acc[i][j] + bias[jj];
                float sg = 1.f / (1.f + __expf(-1.702f * val));
                g_h1[(size_t)m*HID + jj] = val * sg;
            }
        } else {
            // fc2 + residual (d_out holds x_mid) -> d_out
            #pragma unroll
            for (int j = 0; j < 8; j++) {
                int jj = cn + j;
                float val = acc[i][j] + bias[jj];
                size_t idx = (size_t)m*CC + jj;
                Cout[idx] = Cout[idx] + val;
            }
        }
    }
}

// ---------------- attention: one block per (window, head), 64 threads ----------------
__global__ void __launch_bounds__(64) attn_kernel(const float* __restrict__ rpb,
                                                  const int*   __restrict__ relidx,
                                                  const float* __restrict__ mask) {
    int blk  = blockIdx.x;          // b_*HEADS + head
    int head = blk & 7;
    int b_   = blk >> 3;
    int widx = b_ & 63;

    __shared__ float ks[NWIN][HD];
    __shared__ float vs[NWIN][HD];

    int t = threadIdx.x;
    const float* kg = g_k + (size_t)blk * (NWIN*HD);
    const float* vg = g_v + (size_t)blk * (NWIN*HD);
    for (int idx = t; idx < NWIN*HD; idx += 64) {
        ((float*)ks)[idx] = kg[idx];
        ((float*)vs)[idx] = vg[idx];
    }
    __syncthreads();

    if (t < NWIN) {
        float q[HD];
        const float* qg = g_q + (size_t)blk*(NWIN*HD) + (size_t)t*HD;
        #pragma unroll
        for (int d = 0; d < HD; d++) q[d] = qg[d];

        float s[NWIN];
        const int*   ri = relidx + t*NWIN;
        const float* mk = mask + (size_t)widx*(NWIN*NWIN) + t*NWIN;
        float mx = -1e30f;
        #pragma unroll
        for (int m = 0; m < NWIN; m++) {
            float acc = 0.f;
            #pragma unroll
            for (int d = 0; d < HD; d++) acc = fmaf(q[d], ks[m][d], acc);
            acc += rpb[ri[m]*HEADS + head] + mk[m];
            s[m] = acc;
            mx = fmaxf(mx, acc);
        }
        float sum = 0.f;
        #pragma unroll
        for (int m = 0; m < NWIN; m++) { float e = __expf(s[m]-mx); s[m] = e; sum += e; }
        float inv = 1.f/sum;

        float o[HD];
        #pragma unroll
        for (int d = 0; d < HD; d++) o[d] = 0.f;
        #pragma unroll
        for (int m = 0; m < NWIN; m++) {
            float p = s[m];
            #pragma unroll
            for (int d = 0; d < HD; d++) o[d] = fmaf(p, vs[m][d], o[d]);
        }
        float* outp = g_ao + ((size_t)b_*NWIN + t)*CC + head*HD;
        #pragma unroll
        for (int d = 0; d < HD; d++) outp[d] = o[d] * inv;
    }
}

// ---------------- launch ----------------
extern "C" void kernel_launch(void* const* d_in, const int* in_sizes, int n_in,
                              void* d_out, int out_size) {
    const float* x     = (const float*)d_in[0];
    const float* n1g   = (const float*)d_in[1];
    const float* n1b   = (const float*)d_in[2];
    const float* qkvw  = (const float*)d_in[3];
    const float* qkvb  = (const float*)d_in[4];
    const float* rpb   = (const float*)d_in[5];
    const float* projw = (const float*)d_in[6];
    const float* projb = (const float*)d_in[7];
    const float* n2g   = (const float*)d_in[8];
    const float* n2b   = (const float*)d_in[9];
    const float* fc1w  = (const float*)d_in[10];
    const float* fc1b  = (const float*)d_in[11];
    const float* fc2w  = (const float*)d_in[12];
    const float* fc2b  = (const float*)d_in[13];
    const int*   relidx= (const int*)  d_in[14];
    const float* mask  = (const float*)d_in[15];
    float* out = (float*)d_out;

    // 1) LN1 + shift + window partition
    ln1_gather<<<MROWS, 256>>>(x, n1g, n1b);
    // 2) QKV GEMM (M x 768 x 256), scatter into q/k/v, scale q
    sgemm_nt<0,0><<<dim3(768/128, MROWS/128), 256>>>(qkvw, qkvb, nullptr, nullptr, 256);
    // 3) windowed attention with rpb + mask + softmax
    attn_kernel<<<BWIN*HEADS, 64>>>(rpb, relidx, mask);
    // 4) proj GEMM (M x 256 x 256) + window-reverse/shift scatter + residual -> d_out (= x_mid)
    sgemm_nt<1,1><<<dim3(256/128, MROWS/128), 256>>>(projw, projb, x, out, 256);
    // 5) LN2
    ln2_kernel<<<MROWS, 256>>>(out, n2g, n2b);
    // 6) FC1 GEMM (M x 1024 x 256) + fast gelu
    sgemm_nt<2,2><<<dim3(1024/128, MROWS/128), 256>>>(fc1w, fc1b, nullptr, nullptr, 256);
    // 7) FC2 GEMM (M x 256 x 1024) + residual into d_out
    sgemm_nt<3,3><<<dim3(256/128, MROWS/128), 256>>>(fc2w, fc2b, nullptr, out, 1024);
}

// round 5
// speedup vs baseline: 2.7785x; 2.7785x over previous
#include <cuda_runtime.h>
#include <math.h>

// ---------------- problem constants ----------------
#define BB     64
#define HH     56
#define WWID   56
#define CC     256
#define WS     7
#define SHIFT  3
#define HEADS  8
#define HD     32
#define NWIN   49               // tokens per window
#define NW     64               // windows per image (8x8)
#define BWIN   (BB*NW)          // 4096
#define MROWS  (BWIN*NWIN)      // 200704 == B*H*W
#define HID    1024
#define QSCALE 0.17677669529663689f   // 32^-0.5

// ---------------- scratch (device globals; no allocation allowed) ----------------
__device__ float g_ywin[(size_t)MROWS*CC];   // LN1+shift+window-partitioned activations
__device__ float g_q[(size_t)MROWS*CC];      // (B_,HEADS,N,HD), pre-scaled
__device__ float g_k[(size_t)MROWS*CC];
__device__ float g_v[(size_t)MROWS*CC];
__device__ float g_ao[(size_t)MROWS*CC];     // attention out, (B_*N, C) head-interleaved
__device__ float g_ln2[(size_t)MROWS*CC];
__device__ float g_h1[(size_t)MROWS*HID];    // fc1+gelu output

// ---------------- tf32 helpers ----------------
__device__ __forceinline__ unsigned f2tf(float x) {
    unsigned r; asm("cvt.rna.tf32.f32 %0, %1;" : "=r"(r) : "f"(x)); return r;
}
__device__ __forceinline__ void mma_tf32(float* c,
                                         unsigned a0, unsigned a1, unsigned a2, unsigned a3,
                                         unsigned b0, unsigned b1) {
    asm volatile(
        "mma.sync.aligned.m16n8k8.row.col.f32.tf32.tf32.f32 "
        "{%0,%1,%2,%3},{%4,%5,%6,%7},{%8,%9},{%0,%1,%2,%3};"
        : "+f"(c[0]), "+f"(c[1]), "+f"(c[2]), "+f"(c[3])
        : "r"(a0), "r"(a1), "r"(a2), "r"(a3), "r"(b0), "r"(b1));
}

// ---------------- LN helpers ----------------
__device__ __forceinline__ void block_reduce_2(float &s, float &q) {
    #pragma unroll
    for (int o = 16; o > 0; o >>= 1) {
        s += __shfl_xor_sync(0xffffffffu, s, o);
        q += __shfl_xor_sync(0xffffffffu, q, o);
    }
    __shared__ float ss[8], sq[8];
    int lane = threadIdx.x & 31, wid = threadIdx.x >> 5;
    if (lane == 0) { ss[wid] = s; sq[wid] = q; }
    __syncthreads();
    float ts = 0.f, tq = 0.f;
    #pragma unroll
    for (int k = 0; k < 8; k++) { ts += ss[k]; tq += sq[k]; }
    s = ts; q = tq;
}

// LN1 + cyclic shift (-3,-3) + window partition, writes g_ywin row-major (M, C)
__global__ void ln1_gather(const float* __restrict__ x,
                           const float* __restrict__ gam,
                           const float* __restrict__ bet) {
    int r = blockIdx.x, t = threadIdx.x;
    int b_ = r / NWIN, n = r % NWIN;
    int b = b_ >> 6, widx = b_ & 63;
    int wh = widx >> 3, ww = widx & 7;
    int i = n / WS, j = n % WS;
    int h = (wh*WS + i + SHIFT) % HH;
    int w = (ww*WS + j + SHIFT) % WWID;
    size_t src = ((size_t)b*(HH*WWID) + (size_t)h*WWID + w)*CC + t;
    float v = x[src];
    float s = v, q = v*v;
    block_reduce_2(s, q);
    float mean = s * (1.f/CC);
    float var  = q * (1.f/CC) - mean*mean;
    float rstd = rsqrtf(var + 1e-5f);
    g_ywin[(size_t)r*CC + t] = (v - mean)*rstd*gam[t] + bet[t];
}

// LN2 over x_mid (stored in d_out), writes g_ln2
__global__ void ln2_kernel(const float* __restrict__ xin,
                           const float* __restrict__ gam,
                           const float* __restrict__ bet) {
    int r = blockIdx.x, t = threadIdx.x;
    float v = xin[(size_t)r*CC + t];
    float s = v, q = v*v;
    block_reduce_2(s, q);
    float mean = s * (1.f/CC);
    float var  = q * (1.f/CC) - mean*mean;
    float rstd = rsqrtf(var + 1e-5f);
    g_ln2[(size_t)r*CC + t] = (v - mean)*rstd*gam[t] + bet[t];
}

// ---------------- tf32 tensor-core GEMM: C[m,n] = sum_k A[m,k]*Bw[n,k]  (NT) ----------------
// BM=BN=128, BK=16, 256 threads (8 warps), warp tile 64x32 via m16n8k8.
// Smem layout [row][k] padded to stride 20 -> conflict-free fragment loads.
template<int EPI, int ASEL>
__global__ void __launch_bounds__(256) gemm_tf32(const float* __restrict__ Bw,
                                                 const float* __restrict__ bias,
                                                 const float* __restrict__ add_src,
                                                 float* __restrict__ Cout,
                                                 int K) {
    const float* A;
    if      (ASEL == 0) A = g_ywin;
    else if (ASEL == 1) A = g_ao;
    else if (ASEL == 2) A = g_ln2;
    else                A = g_h1;

    __shared__ unsigned As[128*20];
    __shared__ unsigned Bs[128*20];

    int bm = blockIdx.y, bn = blockIdx.x;
    int t    = threadIdx.x;
    int lane = t & 31, wid = t >> 5;
    int wm = wid & 1;          // 0..1  (64-row slabs)
    int wn = wid >> 1;         // 0..3  (32-col slabs)
    int lm = lane >> 2;        // 0..7
    int lq = lane & 3;         // 0..3

    int lr = t >> 1;           // 0..127 : gmem row
    int lcs = (t & 1) * 8;     // 0 or 8 : gmem col segment

    const float* Ablk = A  + (size_t)(bm*128 + lr)*K + lcs;
    const float* Bblk = Bw + (size_t)(bn*128 + lr)*K + lcs;

    float acc[4][4][4];
    #pragma unroll
    for (int i = 0; i < 4; i++)
        #pragma unroll
        for (int j = 0; j < 4; j++)
            #pragma unroll
            for (int e = 0; e < 4; e++) acc[i][j][e] = 0.f;

    for (int k0 = 0; k0 < K; k0 += 16) {
        float4 a0 = *(const float4*)(Ablk + k0);
        float4 a1 = *(const float4*)(Ablk + k0 + 4);
        float4 b0 = *(const float4*)(Bblk + k0);
        float4 b1 = *(const float4*)(Bblk + k0 + 4);
        __syncthreads();
        {
            uint4 ua0 = make_uint4(f2tf(a0.x), f2tf(a0.y), f2tf(a0.z), f2tf(a0.w));
            uint4 ua1 = make_uint4(f2tf(a1.x), f2tf(a1.y), f2tf(a1.z), f2tf(a1.w));
            uint4 ub0 = make_uint4(f2tf(b0.x), f2tf(b0.y), f2tf(b0.z), f2tf(b0.w));
            uint4 ub1 = make_uint4(f2tf(b1.x), f2tf(b1.y), f2tf(b1.z), f2tf(b1.w));
            *(uint4*)&As[lr*20 + lcs]     = ua0;
            *(uint4*)&As[lr*20 + lcs + 4] = ua1;
            *(uint4*)&Bs[lr*20 + lcs]     = ub0;
            *(uint4*)&Bs[lr*20 + lcs + 4] = ub1;
        }
        __syncthreads();
        #pragma unroll
        for (int ks = 0; ks < 16; ks += 8) {
            unsigned af[4][4];
            #pragma unroll
            for (int mt = 0; mt < 4; mt++) {
                int row = wm*64 + mt*16 + lm;
                af[mt][0] = As[(row  )*20 + ks     + lq];
                af[mt][1] = As[(row+8)*20 + ks     + lq];
                af[mt][2] = As[(row  )*20 + ks + 4 + lq];
                af[mt][3] = As[(row+8)*20 + ks + 4 + lq];
            }
            unsigned bf[4][2];
            #pragma unroll
            for (int nt = 0; nt < 4; nt++) {
                int col = wn*32 + nt*8 + lm;
                bf[nt][0] = Bs[col*20 + ks     + lq];
                bf[nt][1] = Bs[col*20 + ks + 4 + lq];
            }
            #pragma unroll
            for (int mt = 0; mt < 4; mt++)
                #pragma unroll
                for (int nt = 0; nt < 4; nt++)
                    mma_tf32(acc[mt][nt], af[mt][0], af[mt][1], af[mt][2], af[mt][3],
                             bf[nt][0], bf[nt][1]);
        }
    }

    // ---------------- fused epilogues ----------------
    #pragma unroll
    for (int mt = 0; mt < 4; mt++) {
        #pragma unroll
        for (int half = 0; half < 2; half++) {
            int m = bm*128 + wm*64 + mt*16 + lm + half*8;
            int b_ = m / NWIN, nn = m % NWIN;
            // proj scatter row (only used by EPI==1)
            size_t drow = 0;
            if (EPI == 1) {
                int b = b_ >> 6, widx = b_ & 63;
                int wh = widx >> 3, ww = widx & 7;
                int ii = nn / WS, jj2 = nn % WS;
                int h = (wh*WS + ii + SHIFT) % HH;
                int w = (ww*WS + jj2 + SHIFT) % WWID;
                drow = (size_t)b*(HH*WWID) + (size_t)h*WWID + w;
            }
            #pragma unroll
            for (int nt = 0; nt < 4; nt++) {
                #pragma unroll
                for (int e = 0; e < 2; e++) {
                    int n = bn*128 + wn*32 + nt*8 + 2*lq + e;
                    float val = acc[mt][nt][half*2 + e] + bias[n];
                    if (EPI == 0) {
                        int part = n >> 8;
                        int c = n & 255;
                        int head = c >> 5, d = c & 31;
                        size_t dst = ((size_t)(b_*HEADS + head)*NWIN + nn)*HD + d;
                        if      (part == 0) g_q[dst] = val * QSCALE;
                        else if (part == 1) g_k[dst] = val;
                        else                g_v[dst] = val;
                    } else if (EPI == 1) {
                        Cout[drow*CC + n] = add_src[drow*CC + n] + val;
                    } else if (EPI == 2) {
                        float sg = 1.f / (1.f + __expf(-1.702f * val));
                        g_h1[(size_t)m*HID + n] = val * sg;
                    } else {
                        size_t idx = (size_t)m*CC + n;
                        Cout[idx] = Cout[idx] + val;
                    }
                }
            }
        }
    }
}

// ---------------- attention: one block per (window, head), 64 threads ----------------
__global__ void __launch_bounds__(64) attn_kernel(const float* __restrict__ rpb,
                                                  const int*   __restrict__ relidx,
                                                  const float* __restrict__ mask) {
    int blk  = blockIdx.x;          // b_*HEADS + head
    int head = blk & 7;
    int b_   = blk >> 3;
    int widx = b_ & 63;

    __shared__ float ks[NWIN][HD];
    __shared__ float vs[NWIN][HD];

    int t = threadIdx.x;
    const float* kg = g_k + (size_t)blk * (NWIN*HD);
    const float* vg = g_v + (size_t)blk * (NWIN*HD);
    for (int idx = t; idx < NWIN*HD; idx += 64) {
        ((float*)ks)[idx] = kg[idx];
        ((float*)vs)[idx] = vg[idx];
    }
    __syncthreads();

    if (t < NWIN) {
        float q[HD];
        const float* qg = g_q + (size_t)blk*(NWIN*HD) + (size_t)t*HD;
        #pragma unroll
        for (int d = 0; d < HD; d++) q[d] = qg[d];

        float s[NWIN];
        const int*   ri = relidx + t*NWIN;
        const float* mk = mask + (size_t)widx*(NWIN*NWIN) + t*NWIN;
        float mx = -1e30f;
        #pragma unroll
        for (int m = 0; m < NWIN; m++) {
            float acc = 0.f;
            #pragma unroll
            for (int d = 0; d < HD; d++) acc = fmaf(q[d], ks[m][d], acc);
            acc += rpb[ri[m]*HEADS + head] + mk[m];
            s[m] = acc;
            mx = fmaxf(mx, acc);
        }
        float sum = 0.f;
        #pragma unroll
        for (int m = 0; m < NWIN; m++) { float e = __expf(s[m]-mx); s[m] = e; sum += e; }
        float inv = 1.f/sum;

        float o[HD];
        #pragma unroll
        for (int d = 0; d < HD; d++) o[d] = 0.f;
        #pragma unroll
        for (int m = 0; m < NWIN; m++) {
            float p = s[m];
            #pragma unroll
            for (int d = 0; d < HD; d++) o[d] = fmaf(p, vs[m][d], o[d]);
        }
        float* outp = g_ao + ((size_t)b_*NWIN + t)*CC + head*HD;
        #pragma unroll
        for (int d = 0; d < HD; d++) outp[d] = o[d] * inv;
    }
}

// ---------------- launch ----------------
extern "C" void kernel_launch(void* const* d_in, const int* in_sizes, int n_in,
                              void* d_out, int out_size) {
    const float* x     = (const float*)d_in[0];
    const float* n1g   = (const float*)d_in[1];
    const float* n1b   = (const float*)d_in[2];
    const float* qkvw  = (const float*)d_in[3];
    const float* qkvb  = (const float*)d_in[4];
    const float* rpb   = (const float*)d_in[5];
    const float* projw = (const float*)d_in[6];
    const float* projb = (const float*)d_in[7];
    const float* n2g   = (const float*)d_in[8];
    const float* n2b   = (const float*)d_in[9];
    const float* fc1w  = (const float*)d_in[10];
    const float* fc1b  = (const float*)d_in[11];
    const float* fc2w  = (const float*)d_in[12];
    const float* fc2b  = (const float*)d_in[13];
    const int*   relidx= (const int*)  d_in[14];
    const float* mask  = (const float*)d_in[15];
    float* out = (float*)d_out;

    // 1) LN1 + shift + window partition
    ln1_gather<<<MROWS, 256>>>(x, n1g, n1b);
    // 2) QKV GEMM (M x 768 x 256), scatter into q/k/v, scale q
    gemm_tf32<0,0><<<dim3(768/128, MROWS/128), 256>>>(qkvw, qkvb, nullptr, nullptr, 256);
    // 3) windowed attention with rpb + mask + softmax
    attn_kernel<<<BWIN*HEADS, 64>>>(rpb, relidx, mask);
    // 4) proj GEMM (M x 256 x 256) + window-reverse/shift scatter + residual -> d_out (= x_mid)
    gemm_tf32<1,1><<<dim3(256/128, MROWS/128), 256>>>(projw, projb, x, out, 256);
    // 5) LN2
    ln2_kernel<<<MROWS, 256>>>(out, n2g, n2b);
    // 6) FC1 GEMM (M x 1024 x 256) + fast gelu
    gemm_tf32<2,2><<<dim3(1024/128, MROWS/128), 256>>>(fc1w, fc1b, nullptr, nullptr, 256);
    // 7) FC2 GEMM (M x 256 x 1024) + residual into d_out
    gemm_tf32<3,3><<<dim3(256/128, MROWS/128), 256>>>(fc2w, fc2b, nullptr, out, 1024);
}

// round 8
// speedup vs baseline: 3.2197x; 1.1588x over previous
#include <cuda_runtime.h>
#include <cuda_fp16.h>
#include <math.h>

// ---------------- problem constants ----------------
#define BB     64
#define HH     56
#define WWID   56
#define CC     256
#define WS     7
#define SHIFT  3
#define HEADS  8
#define HD     32
#define NWIN   49               // tokens per window
#define NW     64               // windows per image (8x8)
#define BWIN   (BB*NW)          // 4096
#define MROWS  (BWIN*NWIN)      // 200704 == B*H*W
#define HID    1024
#define QSCALE 0.17677669529663689f   // 32^-0.5

// smem row stride in half2 words: bank = (36*lm + lq) mod 32 = (4*lm+lq) -> conflict-free
#define SSTR   36

// ---------------- scratch (device globals; no allocation allowed) ----------------
__device__ float g_ywin[(size_t)MROWS*CC];   // LN1+shift+window-partitioned activations
__device__ float g_q[(size_t)MROWS*CC];      // (B_,HEADS,N,HD), pre-scaled
__device__ float g_k[(size_t)MROWS*CC];
__device__ float g_v[(size_t)MROWS*CC];
__device__ float g_ao[(size_t)MROWS*CC];     // attention out, (B_*N, C) head-interleaved
__device__ float g_ln2[(size_t)MROWS*CC];
__device__ float g_h1[(size_t)MROWS*HID];    // fc1+gelu output

// ---------------- fp16 mma helper ----------------
__device__ __forceinline__ void mma_f16(float* c,
                                        unsigned a0, unsigned a1, unsigned a2, unsigned a3,
                                        unsigned b0, unsigned b1) {
    asm volatile(
        "mma.sync.aligned.m16n8k16.row.col.f32.f16.f16.f32 "
        "{%0,%1,%2,%3},{%4,%5,%6,%7},{%8,%9},{%0,%1,%2,%3};"
        : "+f"(c[0]), "+f"(c[1]), "+f"(c[2]), "+f"(c[3])
        : "r"(a0), "r"(a1), "r"(a2), "r"(a3), "r"(b0), "r"(b1));
}
__device__ __forceinline__ unsigned h2pack(float x, float y) {
    __half2 h = __floats2half2_rn(x, y);
    return *(unsigned*)&h;
}

// ---------------- LN helpers ----------------
__device__ __forceinline__ void block_reduce_2(float &s, float &q) {
    #pragma unroll
    for (int o = 16; o > 0; o >>= 1) {
        s += __shfl_xor_sync(0xffffffffu, s, o);
        q += __shfl_xor_sync(0xffffffffu, q, o);
    }
    __shared__ float ss[8], sq[8];
    int lane = threadIdx.x & 31, wid = threadIdx.x >> 5;
    if (lane == 0) { ss[wid] = s; sq[wid] = q; }
    __syncthreads();
    float ts = 0.f, tq = 0.f;
    #pragma unroll
    for (int k = 0; k < 8; k++) { ts += ss[k]; tq += sq[k]; }
    s = ts; q = tq;
}

// LN1 + cyclic shift (-3,-3) + window partition, writes g_ywin row-major (M, C)
__global__ void ln1_gather(const float* __restrict__ x,
                           const float* __restrict__ gam,
                           const float* __restrict__ bet) {
    int r = blockIdx.x, t = threadIdx.x;
    int b_ = r / NWIN, n = r % NWIN;
    int b = b_ >> 6, widx = b_ & 63;
    int wh = widx >> 3, ww = widx & 7;
    int i = n / WS, j = n % WS;
    int h = (wh*WS + i + SHIFT) % HH;
    int w = (ww*WS + j + SHIFT) % WWID;
    size_t src = ((size_t)b*(HH*WWID) + (size_t)h*WWID + w)*CC + t;
    float v = x[src];
    float s = v, q = v*v;
    block_reduce_2(s, q);
    float mean = s * (1.f/CC);
    float var  = q * (1.f/CC) - mean*mean;
    float rstd = rsqrtf(var + 1e-5f);
    g_ywin[(size_t)r*CC + t] = (v - mean)*rstd*gam[t] + bet[t];
}

// LN2 over x_mid (stored in d_out), writes g_ln2
__global__ void ln2_kernel(const float* __restrict__ xin,
                           const float* __restrict__ gam,
                           const float* __restrict__ bet) {
    int r = blockIdx.x, t = threadIdx.x;
    float v = xin[(size_t)r*CC + t];
    float s = v, q = v*v;
    block_reduce_2(s, q);
    float mean = s * (1.f/CC);
    float var  = q * (1.f/CC) - mean*mean;
    float rstd = rsqrtf(var + 1e-5f);
    g_ln2[(size_t)r*CC + t] = (v - mean)*rstd*gam[t] + bet[t];
}

// ---------------- fp16 tensor-core GEMM: C[m,n] = sum_k A[m,k]*Bw[n,k]  (NT) ----------------
// BM=BN=128, BK=16, 256 threads (8 warps), warp tile 64x32 via m16n8k16 (fp32 accum).
// Smem: half2 words, row stride 36 -> conflict-free fragment LDS.32.
template<int EPI, int ASEL>
__global__ void __launch_bounds__(256) gemm_f16(const float* __restrict__ Bw,
                                                const float* __restrict__ bias,
                                                const float* __restrict__ add_src,
                                                float* __restrict__ Cout,
                                                int K) {
    const float* A;
    if      (ASEL == 0) A = g_ywin;
    else if (ASEL == 1) A = g_ao;
    else if (ASEL == 2) A = g_ln2;
    else                A = g_h1;

    __shared__ unsigned As[128*SSTR];   // [row][8 half2-words], stride SSTR
    __shared__ unsigned Bs[128*SSTR];

    int bm = blockIdx.y, bn = blockIdx.x;
    int t    = threadIdx.x;
    int lane = t & 31, wid = t >> 5;
    int wm = wid & 1;          // 0..1  (64-row slabs)
    int wn = wid >> 1;         // 0..3  (32-col slabs)
    int lm = lane >> 2;        // 0..7
    int lq = lane & 3;         // 0..3

    int lr  = t >> 1;          // 0..127 : gmem row
    int lcs = (t & 1) * 8;     // 0 or 8 : gmem col segment
    int sw  = lr*SSTR + (t & 1) * 4;   // smem word base for this thread's stores

    const float* Ablk = A  + (size_t)(bm*128 + lr)*K + lcs;
    const float* Bblk = Bw + (size_t)(bn*128 + lr)*K + lcs;

    float acc[4][4][4];
    #pragma unroll
    for (int i = 0; i < 4; i++)
        #pragma unroll
        for (int j = 0; j < 4; j++)
            #pragma unroll
            for (int e = 0; e < 4; e++) acc[i][j][e] = 0.f;

    for (int k0 = 0; k0 < K; k0 += 16) {
        float4 a0 = *(const float4*)(Ablk + k0);
        float4 a1 = *(const float4*)(Ablk + k0 + 4);
        float4 b0 = *(const float4*)(Bblk + k0);
        float4 b1 = *(const float4*)(Bblk + k0 + 4);
        __syncthreads();
        {
            uint4 ua = make_uint4(h2pack(a0.x,a0.y), h2pack(a0.z,a0.w),
                                  h2pack(a1.x,a1.y), h2pack(a1.z,a1.w));
            uint4 ub = make_uint4(h2pack(b0.x,b0.y), h2pack(b0.z,b0.w),
                                  h2pack(b1.x,b1.y), h2pack(b1.z,b1.w));
            *(uint4*)&As[sw] = ua;
            *(uint4*)&Bs[sw] = ub;
        }
        __syncthreads();
        // one k-step of 16 via m16n8k16
        unsigned af[4][4];
        #pragma unroll
        for (int mt = 0; mt < 4; mt++) {
            int row = wm*64 + mt*16 + lm;
            af[mt][0] = As[(row  )*SSTR + lq];        // rows row,   k 2lq..2lq+1
            af[mt][1] = As[(row+8)*SSTR + lq];        // rows row+8, k 2lq..2lq+1
            af[mt][2] = As[(row  )*SSTR + 4 + lq];    // rows row,   k 8+2lq..
            af[mt][3] = As[(row+8)*SSTR + 4 + lq];    // rows row+8, k 8+2lq..
        }
        unsigned bf[4][2];
        #pragma unroll
        for (int nt = 0; nt < 4; nt++) {
            int col = wn*32 + nt*8 + lm;
            bf[nt][0] = Bs[col*SSTR + lq];
            bf[nt][1] = Bs[col*SSTR + 4 + lq];
        }
        #pragma unroll
        for (int mt = 0; mt < 4; mt++)
            #pragma unroll
            for (int nt = 0; nt < 4; nt++)
                mma_f16(acc[mt][nt], af[mt][0], af[mt][1], af[mt][2], af[mt][3],
                        bf[nt][0], bf[nt][1]);
    }

    // ---------------- fused epilogues ----------------
    #pragma unroll
    for (int mt = 0; mt < 4; mt++) {
        #pragma unroll
        for (int half = 0; half < 2; half++) {
            int m = bm*128 + wm*64 + mt*16 + lm + half*8;
            int b_ = m / NWIN, nn = m % NWIN;
            // proj scatter row (only used by EPI==1)
            size_t drow = 0;
            if (EPI == 1) {
                int b = b_ >> 6, widx = b_ & 63;
                int wh = widx >> 3, ww = widx & 7;
                int ii = nn / WS, jj2 = nn % WS;
                int h = (wh*WS + ii + SHIFT) % HH;
                int w = (ww*WS + jj2 + SHIFT) % WWID;
                drow = (size_t)b*(HH*WWID) + (size_t)h*WWID + w;
            }
            #pragma unroll
            for (int nt = 0; nt < 4; nt++) {
                #pragma unroll
                for (int e = 0; e < 2; e++) {
                    int n = bn*128 + wn*32 + nt*8 + 2*lq + e;
                    float val = acc[mt][nt][half*2 + e] + bias[n];
                    if (EPI == 0) {
                        int part = n >> 8;
                        int c = n & 255;
                        int head = c >> 5, d = c & 31;
                        size_t dst = ((size_t)(b_*HEADS + head)*NWIN + nn)*HD + d;
                        if      (part == 0) g_q[dst] = val * QSCALE;
                        else if (part == 1) g_k[dst] = val;
                        else                g_v[dst] = val;
                    } else if (EPI == 1) {
                        Cout[drow*CC + n] = add_src[drow*CC + n] + val;
                    } else if (EPI == 2) {
                        float sg = 1.f / (1.f + __expf(-1.702f * val));
                        g_h1[(size_t)m*HID + n] = val * sg;
                    } else {
                        size_t idx = (size_t)m*CC + n;
                        Cout[idx] = Cout[idx] + val;
                    }
                }
            }
        }
    }
}

// ---------------- attention: one block per (window, head), 64 threads ----------------
__global__ void __launch_bounds__(64) attn_kernel(const float* __restrict__ rpb,
                                                  const int*   __restrict__ relidx,
                                                  const float* __restrict__ mask) {
    int blk  = blockIdx.x;          // b_*HEADS + head
    int head = blk & 7;
    int b_   = blk >> 3;
    int widx = b_ & 63;

    __shared__ float ks[NWIN][HD];
    __shared__ float vs[NWIN][HD];

    int t = threadIdx.x;
    const float* kg = g_k + (size_t)blk * (NWIN*HD);
    const float* vg = g_v + (size_t)blk * (NWIN*HD);
    for (int idx = t; idx < NWIN*HD; idx += 64) {
        ((float*)ks)[idx] = kg[idx];
        ((float*)vs)[idx] = vg[idx];
    }
    __syncthreads();

    if (t < NWIN) {
        float q[HD];
        const float* qg = g_q + (size_t)blk*(NWIN*HD) + (size_t)t*HD;
        #pragma unroll
        for (int d = 0; d < HD; d++) q[d] = qg[d];

        float s[NWIN];
        const int*   ri = relidx + t*NWIN;
        const float* mk = mask + (size_t)widx*(NWIN*NWIN) + t*NWIN;
        float mx = -1e30f;
        #pragma unroll
        for (int m = 0; m < NWIN; m++) {
            float acc = 0.f;
            #pragma unroll
            for (int d = 0; d < HD; d++) acc = fmaf(q[d], ks[m][d], acc);
            acc += rpb[ri[m]*HEADS + head] + mk[m];
            s[m] = acc;
            mx = fmaxf(mx, acc);
        }
        float sum = 0.f;
        #pragma unroll
        for (int m = 0; m < NWIN; m++) { float e = __expf(s[m]-mx); s[m] = e; sum += e; }
        float inv = 1.f/sum;

        float o[HD];
        #pragma unroll
        for (int d = 0; d < HD; d++) o[d] = 0.f;
        #pragma unroll
        for (int m = 0; m < NWIN; m++) {
            float p = s[m];
            #pragma unroll
            for (int d = 0; d < HD; d++) o[d] = fmaf(p, vs[m][d], o[d]);
        }
        float* outp = g_ao + ((size_t)b_*NWIN + t)*CC + head*HD;
        #pragma unroll
        for (int d = 0; d < HD; d++) outp[d] = o[d] * inv;
    }
}

// ---------------- launch ----------------
extern "C" void kernel_launch(void* const* d_in, const int* in_sizes, int n_in,
                              void* d_out, int out_size) {
    const float* x     = (const float*)d_in[0];
    const float* n1g   = (const float*)d_in[1];
    const float* n1b   = (const float*)d_in[2];
    const float* qkvw  = (const float*)d_in[3];
    const float* qkvb  = (const float*)d_in[4];
    const float* rpb   = (const float*)d_in[5];
    const float* projw = (const float*)d_in[6];
    const float* projb = (const float*)d_in[7];
    const float* n2g   = (const float*)d_in[8];
    const float* n2b   = (const float*)d_in[9];
    const float* fc1w  = (const float*)d_in[10];
    const float* fc1b  = (const float*)d_in[11];
    const float* fc2w  = (const float*)d_in[12];
    const float* fc2b  = (const float*)d_in[13];
    const int*   relidx= (const int*)  d_in[14];
    const float* mask  = (const float*)d_in[15];
    float* out = (float*)d_out;

    // 1) LN1 + shift + window partition
    ln1_gather<<<MROWS, 256>>>(x, n1g, n1b);
    // 2) QKV GEMM (M x 768 x 256), scatter into q/k/v, scale q
    gemm_f16<0,0><<<dim3(768/128, MROWS/128), 256>>>(qkvw, qkvb, nullptr, nullptr, 256);
    // 3) windowed attention with rpb + mask + softmax
    attn_kernel<<<BWIN*HEADS, 64>>>(rpb, relidx, mask);
    // 4) proj GEMM (M x 256 x 256) + window-reverse/shift scatter + residual -> d_out (= x_mid)
    gemm_f16<1,1><<<dim3(256/128, MROWS/128), 256>>>(projw, projb, x, out, 256);
    // 5) LN2
    ln2_kernel<<<MROWS, 256>>>(out, n2g, n2b);
    // 6) FC1 GEMM (M x 1024 x 256) + fast gelu
    gemm_f16<2,2><<<dim3(1024/128, MROWS/128), 256>>>(fc1w, fc1b, nullptr, nullptr, 256);
    // 7) FC2 GEMM (M x 256 x 1024) + residual into d_out
    gemm_f16<3,3><<<dim3(256/128, MROWS/128), 256>>>(fc2w, fc2b, nullptr, out, 1024);
}

// round 12
// speedup vs baseline: 4.5206x; 1.4040x over previous
#include <cuda_runtime.h>
#include <cuda_fp16.h>
#include <math.h>

// ---------------- problem constants ----------------
#define BB     64
#define HH     56
#define WWID   56
#define CC     256
#define WS     7
#define SHIFT  3
#define HEADS  8
#define HD     32
#define NWIN   49               // tokens per window
#define NW     64               // windows per image (8x8)
#define BWIN   (BB*NW)          // 4096
#define MROWS  (BWIN*NWIN)      // 200704 == B*H*W
#define HID    1024
#define QSCALE 0.17677669529663689f   // 32^-0.5

// smem row stride in half2 words: bank = (36*lm + lq) mod 32 -> conflict-free fragment LDS
#define SSTR        36
#define STAGE_WORDS (128*SSTR)          // one 128x16 tile of half2 words
#define SMEM_WORDS  (4*STAGE_WORDS)     // As0,As1,Bs0,Bs1
#define SMEM_BYTES  (SMEM_WORDS*4)      // 73728

// ---------------- scratch (device globals; no allocation allowed) ----------------
__device__ __half g_ywin[(size_t)MROWS*CC];   // LN1+shift+window activations (fp16)
__device__ float  g_q[(size_t)MROWS*CC];      // (B_,HEADS,N,HD), pre-scaled
__device__ float  g_k[(size_t)MROWS*CC];
__device__ float  g_v[(size_t)MROWS*CC];
__device__ __half g_ao[(size_t)MROWS*CC];     // attention out (fp16)
__device__ __half g_ln2[(size_t)MROWS*CC];    // LN2 out (fp16)
__device__ __half g_h1[(size_t)MROWS*HID];    // fc1+gelu out (fp16)
// fp16 weight copies
__device__ __half g_wqkv[768*256];
__device__ __half g_wproj[256*256];
__device__ __half g_wfc1[HID*256];
__device__ __half g_wfc2[256*HID];

// ---------------- helpers ----------------
__device__ __forceinline__ void mma_f16(float* c,
                                        unsigned a0, unsigned a1, unsigned a2, unsigned a3,
                                        unsigned b0, unsigned b1) {
    asm volatile(
        "mma.sync.aligned.m16n8k16.row.col.f32.f16.f16.f32 "
        "{%0,%1,%2,%3},{%4,%5,%6,%7},{%8,%9},{%0,%1,%2,%3};"
        : "+f"(c[0]), "+f"(c[1]), "+f"(c[2]), "+f"(c[3])
        : "r"(a0), "r"(a1), "r"(a2), "r"(a3), "r"(b0), "r"(b1));
}
__device__ __forceinline__ void cp_async16(unsigned saddr, const void* gptr) {
    asm volatile("cp.async.cg.shared.global [%0], [%1], 16;" :: "r"(saddr), "l"(gptr));
}
__device__ __forceinline__ void cp_commit() { asm volatile("cp.async.commit_group;"); }
template<int N> __device__ __forceinline__ void cp_wait() {
    asm volatile("cp.async.wait_group %0;" :: "n"(N));
}

// weight fp32 -> fp16 (vectorized by 4)
template<int W>
__global__ void f2h_w(const float4* __restrict__ src, int n4) {
    __half* dst;
    if      (W == 0) dst = g_wqkv;
    else if (W == 1) dst = g_wproj;
    else if (W == 2) dst = g_wfc1;
    else             dst = g_wfc2;
    int i = blockIdx.x*256 + threadIdx.x;
    if (i < n4) {
        float4 v = src[i];
        __half2* d2 = (__half2*)dst;
        d2[2*i]   = __floats2half2_rn(v.x, v.y);
        d2[2*i+1] = __floats2half2_rn(v.z, v.w);
    }
}

// ---------------- LN helpers ----------------
__device__ __forceinline__ void block_reduce_2(float &s, float &q) {
    #pragma unroll
    for (int o = 16; o > 0; o >>= 1) {
        s += __shfl_xor_sync(0xffffffffu, s, o);
        q += __shfl_xor_sync(0xffffffffu, q, o);
    }
    __shared__ float ss[8], sq[8];
    int lane = threadIdx.x & 31, wid = threadIdx.x >> 5;
    if (lane == 0) { ss[wid] = s; sq[wid] = q; }
    __syncthreads();
    float ts = 0.f, tq = 0.f;
    #pragma unroll
    for (int k = 0; k < 8; k++) { ts += ss[k]; tq += sq[k]; }
    s = ts; q = tq;
}

// LN1 + cyclic shift (-3,-3) + window partition -> g_ywin (fp16)
__global__ void ln1_gather(const float* __restrict__ x,
                           const float* __restrict__ gam,
                           const float* __restrict__ bet) {
    int r = blockIdx.x, t = threadIdx.x;
    int b_ = r / NWIN, n = r % NWIN;
    int b = b_ >> 6, widx = b_ & 63;
    int wh = widx >> 3, ww = widx & 7;
    int i = n / WS, j = n % WS;
    int h = (wh*WS + i + SHIFT) % HH;
    int w = (ww*WS + j + SHIFT) % WWID;
    size_t src = ((size_t)b*(HH*WWID) + (size_t)h*WWID + w)*CC + t;
    float v = x[src];
    float s = v, q = v*v;
    block_reduce_2(s, q);
    float mean = s * (1.f/CC);
    float var  = q * (1.f/CC) - mean*mean;
    float rstd = rsqrtf(var + 1e-5f);
    g_ywin[(size_t)r*CC + t] = __float2half((v - mean)*rstd*gam[t] + bet[t]);
}

// LN2 over x_mid (in d_out) -> g_ln2 (fp16)
__global__ void ln2_kernel(const float* __restrict__ xin,
                           const float* __restrict__ gam,
                           const float* __restrict__ bet) {
    int r = blockIdx.x, t = threadIdx.x;
    float v = xin[(size_t)r*CC + t];
    float s = v, q = v*v;
    block_reduce_2(s, q);
    float mean = s * (1.f/CC);
    float var  = q * (1.f/CC) - mean*mean;
    float rstd = rsqrtf(var + 1e-5f);
    g_ln2[(size_t)r*CC + t] = __float2half((v - mean)*rstd*gam[t] + bet[t]);
}

// ---------------- fp16 GEMM, cp.async double-buffered ----------------
// C[m,n] = sum_k A[m,k]*Bw[n,k], A/B fp16 in gmem, BM=BN=128, BK=16, 8 warps,
// warp tile 64x32 (m16n8k16, fp32 accum). P: 0=qkv, 1=proj, 2=fc1, 3=fc2.
template<int P>
__global__ void __launch_bounds__(256) gemm_f16(const float* __restrict__ bias,
                                                const float* __restrict__ add_src,
                                                float* __restrict__ Cout,
                                                int K) {
    const __half *A, *Bw;
    if      (P == 0) { A = g_ywin; Bw = g_wqkv; }
    else if (P == 1) { A = g_ao;   Bw = g_wproj; }
    else if (P == 2) { A = g_ln2;  Bw = g_wfc1; }
    else             { A = g_h1;   Bw = g_wfc2; }

    extern __shared__ unsigned smemPool[];   // [As0|As1|Bs0|Bs1]
    unsigned sbase = (unsigned)__cvta_generic_to_shared(smemPool);

    int bm = blockIdx.y, bn = blockIdx.x;
    int t    = threadIdx.x;
    int lane = t & 31, wid = t >> 5;
    int wm = wid & 1;          // 0..1  (64-row slabs)
    int wn = wid >> 1;         // 0..3  (32-col slabs)
    int lm = lane >> 2;        // 0..7
    int lq = lane & 3;         // 0..3

    int lr = t >> 1;           // 0..127 : row handled by this thread
    int sw = lr*SSTR + (t & 1) * 4;     // smem word offset within a stage

    const __half* Ag = A  + (size_t)(bm*128 + lr)*K + (t & 1)*8;
    const __half* Bg = Bw + (size_t)(bn*128 + lr)*K + (t & 1)*8;

    float acc[4][4][4];
    #pragma unroll
    for (int i = 0; i < 4; i++)
        #pragma unroll
        for (int j = 0; j < 4; j++)
            #pragma unroll
            for (int e = 0; e < 4; e++) acc[i][j][e] = 0.f;

    int niter = K >> 4;
    // prologue: stage 0
    cp_async16(sbase + (0*STAGE_WORDS + sw)*4, Ag);
    cp_async16(sbase + (2*STAGE_WORDS + sw)*4, Bg);
    cp_commit();

    for (int i = 0; i < niter; i++) {
        if (i + 1 < niter) {
            int nb = (i + 1) & 1;
            cp_async16(sbase + ((nb    )*STAGE_WORDS + sw)*4, Ag + (i+1)*16);
            cp_async16(sbase + ((2 + nb)*STAGE_WORDS + sw)*4, Bg + (i+1)*16);
            cp_commit();
            cp_wait<1>();
        } else {
            cp_wait<0>();
        }
        __syncthreads();

        const unsigned* As = smemPool + (i & 1)*STAGE_WORDS;
        const unsigned* Bs = smemPool + (2 + (i & 1))*STAGE_WORDS;

        unsigned af[4][4];
        #pragma unroll
        for (int mt = 0; mt < 4; mt++) {
            int row = wm*64 + mt*16 + lm;
            af[mt][0] = As[(row  )*SSTR + lq];
            af[mt][1] = As[(row+8)*SSTR + lq];
            af[mt][2] = As[(row  )*SSTR + 4 + lq];
            af[mt][3] = As[(row+8)*SSTR + 4 + lq];
        }
        unsigned bf[4][2];
        #pragma unroll
        for (int nt = 0; nt < 4; nt++) {
            int col = wn*32 + nt*8 + lm;
            bf[nt][0] = Bs[col*SSTR + lq];
            bf[nt][1] = Bs[col*SSTR + 4 + lq];
        }
        #pragma unroll
        for (int mt = 0; mt < 4; mt++)
            #pragma unroll
            for (int nt = 0; nt < 4; nt++)
                mma_f16(acc[mt][nt], af[mt][0], af[mt][1], af[mt][2], af[mt][3],
                        bf[nt][0], bf[nt][1]);
        __syncthreads();
    }

    // ---------------- fused epilogues ----------------
    #pragma unroll
    for (int mt = 0; mt < 4; mt++) {
        #pragma unroll
        for (int half = 0; half < 2; half++) {
            int m = bm*128 + wm*64 + mt*16 + lm + half*8;
            int b_ = m / NWIN, nn = m % NWIN;
            size_t drow = 0;
            if (P == 1) {
                int b = b_ >> 6, widx = b_ & 63;
                int wh = widx >> 3, ww = widx & 7;
                int ii = nn / WS, jj2 = nn % WS;
                int h = (wh*WS + ii + SHIFT) % HH;
                int w = (ww*WS + jj2 + SHIFT) % WWID;
                drow = (size_t)b*(HH*WWID) + (size_t)h*WWID + w;
            }
            #pragma unroll
            for (int nt = 0; nt < 4; nt++) {
                int n0 = bn*128 + wn*32 + nt*8 + 2*lq;   // even; n0,n0+1 contiguous
                float v0 = acc[mt][nt][half*2 + 0] + bias[n0];
                float v1 = acc[mt][nt][half*2 + 1] + bias[n0+1];
                if (P == 0) {
                    // qkv scatter: both elems same part/head (n0 even)
                    int part = n0 >> 8;
                    int c = n0 & 255;
                    int head = c >> 5, d = c & 31;
                    size_t dst = ((size_t)(b_*HEADS + head)*NWIN + nn)*HD + d;
                    if (part == 0) {
                        *(float2*)&g_q[dst] = make_float2(v0*QSCALE, v1*QSCALE);
                    } else if (part == 1) {
                        *(float2*)&g_k[dst] = make_float2(v0, v1);
                    } else {
                        *(float2*)&g_v[dst] = make_float2(v0, v1);
                    }
                } else if (P == 1) {
                    size_t idx = drow*CC + n0;
                    float2 r = *(const float2*)&add_src[idx];
                    *(float2*)&Cout[idx] = make_float2(r.x + v0, r.y + v1);
                } else if (P == 2) {
                    float s0 = 1.f / (1.f + __expf(-1.702f * v0));
                    float s1 = 1.f / (1.f + __expf(-1.702f * v1));
                    *(__half2*)&g_h1[(size_t)m*HID + n0] = __floats2half2_rn(v0*s0, v1*s1);
                } else {
                    size_t idx = (size_t)m*CC + n0;
                    float2 r = *(const float2*)&Cout[idx];
                    *(float2*)&Cout[idx] = make_float2(r.x + v0, r.y + v1);
                }
            }
        }
    }
}

// ---------------- attention: one block per (window, head), 64 threads ----------------
__global__ void __launch_bounds__(64) attn_kernel(const float* __restrict__ rpb,
                                                  const int*   __restrict__ relidx,
                                                  const float* __restrict__ mask) {
    int blk  = blockIdx.x;          // b_*HEADS + head
    int head = blk & 7;
    int b_   = blk >> 3;
    int widx = b_ & 63;

    __shared__ float ks[NWIN][HD];
    __shared__ float vs[NWIN][HD];

    int t = threadIdx.x;
    const float* kg = g_k + (size_t)blk * (NWIN*HD);
    const float* vg = g_v + (size_t)blk * (NWIN*HD);
    for (int idx = t; idx < NWIN*HD; idx += 64) {
        ((float*)ks)[idx] = kg[idx];
        ((float*)vs)[idx] = vg[idx];
    }
    __syncthreads();

    if (t < NWIN) {
        float q[HD];
        const float* qg = g_q + (size_t)blk*(NWIN*HD) + (size_t)t*HD;
        #pragma unroll
        for (int d = 0; d < HD; d++) q[d] = qg[d];

        float s[NWIN];
        const int*   ri = relidx + t*NWIN;
        const float* mk = mask + (size_t)widx*(NWIN*NWIN) + t*NWIN;
        float mx = -1e30f;
        #pragma unroll
        for (int m = 0; m < NWIN; m++) {
            float acc = 0.f;
            #pragma unroll
            for (int d = 0; d < HD; d++) acc = fmaf(q[d], ks[m][d], acc);
            acc += rpb[ri[m]*HEADS + head] + mk[m];
            s[m] = acc;
            mx = fmaxf(mx, acc);
        }
        float sum = 0.f;
        #pragma unroll
        for (int m = 0; m < NWIN; m++) { float e = __expf(s[m]-mx); s[m] = e; sum += e; }
        float inv = 1.f/sum;

        float o[HD];
        #pragma unroll
        for (int d = 0; d < HD; d++) o[d] = 0.f;
        #pragma unroll
        for (int m = 0; m < NWIN; m++) {
            float p = s[m];
            #pragma unroll
            for (int d = 0; d < HD; d++) o[d] = fmaf(p, vs[m][d], o[d]);
        }
        __half* outp = g_ao + ((size_t)b_*NWIN + t)*CC + head*HD;
        #pragma unroll
        for (int d = 0; d < HD; d += 2)
            *(__half2*)&outp[d] = __floats2half2_rn(o[d]*inv, o[d+1]*inv);
    }
}

// ---------------- launch ----------------
extern "C" void kernel_launch(void* const* d_in, const int* in_sizes, int n_in,
                              void* d_out, int out_size) {
    const float* x     = (const float*)d_in[0];
    const float* n1g   = (const float*)d_in[1];
    const float* n1b   = (const float*)d_in[2];
    const float* qkvw  = (const float*)d_in[3];
    const float* qkvb  = (const float*)d_in[4];
    const float* rpb   = (const float*)d_in[5];
    const float* projw = (const float*)d_in[6];
    const float* projb = (const float*)d_in[7];
    const float* n2g   = (const float*)d_in[8];
    const float* n2b   = (const float*)d_in[9];
    const float* fc1w  = (const float*)d_in[10];
    const float* fc1b  = (const float*)d_in[11];
    const float* fc2w  = (const float*)d_in[12];
    const float* fc2b  = (const float*)d_in[13];
    const int*   relidx= (const int*)  d_in[14];
    const float* mask  = (const float*)d_in[15];
    float* out = (float*)d_out;

    // opt-in to 72KB dynamic smem (host-side attribute set; not a stream op, capture-safe)
    cudaFuncSetAttribute(gemm_f16<0>, cudaFuncAttributeMaxDynamicSharedMemorySize, SMEM_BYTES);
    cudaFuncSetAttribute(gemm_f16<1>, cudaFuncAttributeMaxDynamicSharedMemorySize, SMEM_BYTES);
    cudaFuncSetAttribute(gemm_f16<2>, cudaFuncAttributeMaxDynamicSharedMemorySize, SMEM_BYTES);
    cudaFuncSetAttribute(gemm_f16<3>, cudaFuncAttributeMaxDynamicSharedMemorySize, SMEM_BYTES);

    // 0) weights -> fp16
    f2h_w<0><<<(768*256/4 + 255)/256, 256>>>((const float4*)qkvw,  768*256/4);
    f2h_w<1><<<(256*256/4 + 255)/256, 256>>>((const float4*)projw, 256*256/4);
    f2h_w<2><<<(HID*256/4 + 255)/256, 256>>>((const float4*)fc1w,  HID*256/4);
    f2h_w<3><<<(256*HID/4 + 255)/256, 256>>>((const float4*)fc2w,  256*HID/4);

    // 1) LN1 + shift + window partition (fp16 out)
    ln1_gather<<<MROWS, 256>>>(x, n1g, n1b);
    // 2) QKV GEMM (M x 768 x 256) -> q/k/v fp32, q pre-scaled
    gemm_f16<0><<<dim3(768/128, MROWS/128), 256, SMEM_BYTES>>>(qkvb, nullptr, nullptr, 256);
    // 3) windowed attention (fp32 math, fp16 out)
    attn_kernel<<<BWIN*HEADS, 64>>>(rpb, relidx, mask);
    // 4) proj GEMM + reverse-shift scatter + residual -> d_out (= x_mid, fp32)
    gemm_f16<1><<<dim3(256/128, MROWS/128), 256, SMEM_BYTES>>>(projb, x, out, 256);
    // 5) LN2 (fp16 out)
    ln2_kernel<<<MROWS, 256>>>(out, n2g, n2b);
    // 6) FC1 GEMM + fast gelu (fp16 out)
    gemm_f16<2><<<dim3(1024/128, MROWS/128), 256, SMEM_BYTES>>>(fc1b, nullptr, nullptr, 256);
    // 7) FC2 GEMM + residual into d_out
    gemm_f16<3><<<dim3(256/128, MROWS/128), 256, SMEM_BYTES>>>(fc2b, nullptr, out, 1024);
}